// round 15
// baseline (speedup 1.0000x reference)
#include <cuda_runtime.h>
#include <cuda_fp16.h>
#include <math.h>
#include <stdint.h>

#define NEXP 8
#define DDIM 2048
#define FDIM 1024
#define MAXT 2048
#define MAXSLOT (2*MAXT)
#define PITCH 40   // halves per 32-k row (64B data + 16B pad)

#define WELEM ((size_t)NEXP*FDIM*DDIM)   // 16777216 per tensor
#define EW    ((size_t)FDIM*DDIM)        // per-expert elements
#define WG_H ((size_t)0)
#define WU_H (WELEM)
#define WD_H (2*WELEM)

// ---------------- device scratch --------------------------------------------
__device__ int   g_cnt[NEXP];
__device__ int   g_off[NEXP];
__device__ int   g_list[NEXP*MAXT];
__device__ float g_wte[NEXP*MAXT];
__device__ __half g_xh[(size_t)MAXT*DDIM];
__device__ __half g_hh[(size_t)MAXSLOT*FDIM];
__device__ __half g_whalf[3*WELEM];   // 100 MB pre-converted fp16 weights

// ---------------- helpers ----------------------------------------------------
__device__ __forceinline__ uint32_t s2u(const void* p) {
    return (uint32_t)__cvta_generic_to_shared(p);
}
__device__ __forceinline__ void ldsm4(uint32_t* r, uint32_t a) {
    asm volatile("ldmatrix.sync.aligned.m8n8.x4.shared.b16 {%0,%1,%2,%3}, [%4];"
                 : "=r"(r[0]), "=r"(r[1]), "=r"(r[2]), "=r"(r[3]) : "r"(a));
}
__device__ __forceinline__ void mma16816(float* c, const uint32_t* a,
                                         const uint32_t* b) {
    asm volatile(
        "mma.sync.aligned.m16n8k16.row.col.f32.f16.f16.f32 "
        "{%0,%1,%2,%3}, {%4,%5,%6,%7}, {%8,%9}, {%0,%1,%2,%3};"
        : "+f"(c[0]), "+f"(c[1]), "+f"(c[2]), "+f"(c[3])
        : "r"(a[0]), "r"(a[1]), "r"(a[2]), "r"(a[3]), "r"(b[0]), "r"(b[1]));
}
__device__ __forceinline__ void cp16(uint32_t dst, const void* src, int sz) {
    asm volatile("cp.async.ca.shared.global [%0], [%1], 16, %2;"
                 :: "r"(dst), "l"(src), "r"(sz) : "memory");
}
__device__ __forceinline__ void cp_commit() {
    asm volatile("cp.async.commit_group;" ::: "memory");
}
__device__ __forceinline__ void cp_wait1() {
    asm volatile("cp.async.wait_group 1;" ::: "memory");
}
__device__ __forceinline__ void cp_wait0() {
    asm volatile("cp.async.wait_group 0;" ::: "memory");
}
__device__ __forceinline__ uint32_t pack2h(__half a, __half b) {
    return ((uint32_t)__half_as_ushort(b) << 16) | __half_as_ushort(a);
}
__device__ __forceinline__ uint32_t cvt2h(float a, float b) {
    return pack2h(__float2half_rn(a), __float2half_rn(b));
}
__device__ __forceinline__ void red2(float* addr, float a, float b) {
    asm volatile("red.global.add.v2.f32 [%0], {%1, %2};"
                 :: "l"(addr), "f"(a), "f"(b) : "memory");
}

// ---------------- small kernels ---------------------------------------------
__global__ void presplit_w(const float* __restrict__ src,
                           __half* __restrict__ dh, int n16) {
    int i = blockIdx.x * blockDim.x + threadIdx.x;
    if (i >= n16) return;
    const float4* s = (const float4*)src + i * 4;
    float4 v0 = __ldcs(s), v1 = __ldcs(s + 1), v2 = __ldcs(s + 2), v3 = __ldcs(s + 3);
    uint4 o0 = make_uint4(cvt2h(v0.x, v0.y), cvt2h(v0.z, v0.w),
                          cvt2h(v1.x, v1.y), cvt2h(v1.z, v1.w));
    uint4 o1 = make_uint4(cvt2h(v2.x, v2.y), cvt2h(v2.z, v2.w),
                          cvt2h(v3.x, v3.y), cvt2h(v3.z, v3.w));
    uint4* d = (uint4*)dh + i * 2;
    __stcs(d, o0);
    __stcs(d + 1, o1);
}

__global__ void presplit_x(const float* __restrict__ x, int n4) {
    int i = blockIdx.x * blockDim.x + threadIdx.x;
    if (blockIdx.x == 0 && threadIdx.x < NEXP) g_cnt[threadIdx.x] = 0;
    if (i >= n4) return;
    float4 v = ((const float4*)x)[i];
    ((uint2*)g_xh)[i] = make_uint2(cvt2h(v.x, v.y), cvt2h(v.z, v.w));
}

__global__ void zero_out(float* __restrict__ out, int n4) {
    int i = blockIdx.x * blockDim.x + threadIdx.x;
    if (i < n4)
        __stcs((float4*)out + i, make_float4(0.f, 0.f, 0.f, 0.f));
}

__global__ void router_kernel(const float* __restrict__ x,
                              const float* __restrict__ gw,
                              float* __restrict__ logits_out,
                              int write_logits) {
    __shared__ float xs[DDIM];
    __shared__ float lg[NEXP];
    int t = blockIdx.x;
    const float* xr = x + (size_t)t * DDIM;
    for (int i = threadIdx.x; i < DDIM; i += blockDim.x) xs[i] = xr[i];
    __syncthreads();

    int w = threadIdx.x >> 5, lane = threadIdx.x & 31;
    if (w < NEXP) {
        const float* g = gw + (size_t)w * DDIM;
        float s = 0.f;
        for (int d = lane; d < DDIM; d += 32) s = fmaf(xs[d], g[d], s);
        for (int o = 16; o; o >>= 1) s += __shfl_xor_sync(0xffffffffu, s, o);
        if (lane == 0) lg[w] = s;
    }
    __syncthreads();

    if (threadIdx.x == 0) {
        float l[NEXP], p[NEXP];
        float m = -1e30f;
        for (int e = 0; e < NEXP; e++) {
            l[e] = lg[e];
            if (write_logits) logits_out[(size_t)t * NEXP + e] = l[e];
            m = fmaxf(m, l[e]);
        }
        float se = 0.f;
        for (int e = 0; e < NEXP; e++) { p[e] = expf(l[e] - m); se += p[e]; }
        float inv = 1.f / se;
        for (int e = 0; e < NEXP; e++) p[e] *= inv;
        int i1 = 0;
        for (int e = 1; e < NEXP; e++) if (p[e] > p[i1]) i1 = e;
        int i2 = -1;
        for (int e = 0; e < NEXP; e++) {
            if (e == i1) continue;
            if (i2 < 0 || p[e] > p[i2]) i2 = e;
        }
        float s12 = p[i1] + p[i2];
        float w1 = p[i1] / s12, w2 = p[i2] / s12;
        int p1 = atomicAdd(&g_cnt[i1], 1);
        g_list[i1 * MAXT + p1] = t;
        g_wte[i1 * MAXT + p1] = w1;
        int p2 = atomicAdd(&g_cnt[i2], 1);
        g_list[i2 * MAXT + p2] = t;
        g_wte[i2 * MAXT + p2] = w2;
    }
}

__global__ void prefix_kernel() {
    int o = 0;
    for (int e = 0; e < NEXP; e++) { g_off[e] = o; o += g_cnt[e]; }
}

extern __shared__ __align__(16) char dynsm[];

// ---------------- gate+up HMMA kernel (2-expert batch) -----------------------
// CTA: 128 slots x 64 f-cols. Warps 0-3: gate (m64xn32), warps 4-7: up.
// stage (bytes): A 0 | GH 10240 | UH 15360   (20480 total)
#define GU_ST 20480
#define GU_DYN (3*GU_ST)

__global__ __launch_bounds__(256, 2)
void gateup_mma(int ebase) {
    int e = ebase + blockIdx.z;
    int n = g_cnt[e];
    int r0 = blockIdx.y * 128;
    if (r0 >= n) return;
    int f0 = blockIdx.x * 64;

    __shared__ int toks[128];
    int tid = threadIdx.x, lane = tid & 31, wid = tid >> 5;
    uint32_t smb = s2u(dynsm);

    if (tid < 128) {
        int r = r0 + tid;
        toks[tid] = (r < n) ? g_list[e * MAXT + r] : -1;
    }
    __syncthreads();

    int arow = tid & 127, aseg = tid >> 7;       // A loader
    int bq = tid >> 7, bhalf = (tid >> 6) & 1, brow = tid & 63;  // B loader
    size_t bsrcoff = (bq ? WU_H : WG_H) +
                     (size_t)e * EW + (size_t)(f0 + brow) * DDIM + bhalf * 16;
    uint32_t bdst = (uint32_t)(10240 + bq * 5120 + brow * (PITCH * 2) + bhalf * 32);

    auto issue = [&](int k0, int st) {
        {
            int tk = toks[arow];
            uint32_t d = smb + st * GU_ST + (arow * PITCH + aseg * 16) * 2;
            const __half* sh = g_xh + ((size_t)(tk < 0 ? 0 : tk) * DDIM + k0 + aseg * 16);
            int sz = (tk < 0) ? 0 : 16;
            cp16(d,      sh,     sz);
            cp16(d + 16, sh + 8, sz);
        }
        {
            const __half* s = g_whalf + bsrcoff + k0;
            uint32_t d = smb + st * GU_ST + bdst;
            cp16(d,      s,     16);
            cp16(d + 16, s + 8, 16);
        }
    };

    float acc[4][4][4];
#pragma unroll
    for (int mt = 0; mt < 4; mt++)
#pragma unroll
        for (int nt = 0; nt < 4; nt++)
#pragma unroll
            for (int j = 0; j < 4; j++) acc[mt][nt][j] = 0.f;

    int isUp = wid >> 2;
    int wid2 = wid & 3;
    int m0 = (wid2 & 1) * 64, n0 = (wid2 >> 1) * 32;
    int wsec = isUp ? 15360 : 10240;
    int mat = lane >> 3, rowin = lane & 7;

    auto compute_slab = [&](int st, int s) {
        uint32_t base = smb + st * GU_ST;
        int kc = s * 16;
        uint32_t ah[4][4];
#pragma unroll
        for (int mt = 0; mt < 4; mt++) {
            uint32_t a = base +
                ((m0 + mt * 16 + (mat & 1) * 8 + rowin) * PITCH + kc + (mat >> 1) * 8) * 2;
            ldsm4(ah[mt], a);
        }
        uint32_t bh[8];
#pragma unroll
        for (int h16 = 0; h16 < 2; h16++) {
            uint32_t a = base + wsec +
                ((n0 + h16 * 16 + (mat >> 1) * 8 + rowin) * PITCH + kc + (mat & 1) * 8) * 2;
            ldsm4(&bh[h16 * 4], a);
        }
#pragma unroll
        for (int mt = 0; mt < 4; mt++)
#pragma unroll
            for (int nt = 0; nt < 4; nt++)
                mma16816(acc[mt][nt], ah[mt], &bh[nt * 2]);
    };

    issue(0, 0); cp_commit();
    issue(32, 1); cp_commit();

    const int C = DDIM / 32;  // 64
    int cbuf = 0, ibuf = 2;
    for (int c = 0; c < C; c++) {
        if (c + 2 < C) cp_wait1(); else cp_wait0();
        __syncthreads();
        compute_slab(cbuf, 0);
        compute_slab(cbuf, 1);
        if (c + 2 < C) {
            issue((c + 2) * 32, ibuf);
            cp_commit();
            ibuf = (ibuf == 2) ? 0 : ibuf + 1;
        }
        cbuf = (cbuf == 2) ? 0 : cbuf + 1;
    }

    // ---- epilogue: gate warps publish G to smem, up warps combine + weight --
    __syncthreads();
    float* gsm = (float*)dynsm;   // 128 x 68 fp32 = 34816 B
    if (!isUp) {
#pragma unroll
        for (int mt = 0; mt < 4; mt++)
#pragma unroll
            for (int nt = 0; nt < 4; nt++) {
                int rb = m0 + mt * 16 + (lane >> 2);
                int col = n0 + nt * 8 + 2 * (lane & 3);
#pragma unroll
                for (int h = 0; h < 2; h++) {
                    int r = rb + h * 8;
                    *(float2*)(gsm + r * 68 + col) =
                        make_float2(acc[mt][nt][2*h], acc[mt][nt][2*h+1]);
                }
            }
    }
    __syncthreads();
    if (isUp) {
        int hbase = g_off[e];
#pragma unroll
        for (int mt = 0; mt < 4; mt++)
#pragma unroll
            for (int nt = 0; nt < 4; nt++) {
                int rb = m0 + mt * 16 + (lane >> 2);
                int col = n0 + nt * 8 + 2 * (lane & 3);
#pragma unroll
                for (int h = 0; h < 2; h++) {
                    int r = rb + h * 8;
                    if (r0 + r < n) {
                        float rw = g_wte[e * MAXT + r0 + r];
                        float2 g = *(float2*)(gsm + r * 68 + col);
                        float u0 = acc[mt][nt][2*h], u1 = acc[mt][nt][2*h+1];
                        float h0 = rw * g.x * u0 / (1.f + __expf(-g.x));
                        float h1 = rw * g.y * u1 / (1.f + __expf(-g.y));
                        size_t ix = (size_t)(hbase + r0 + r) * FDIM + f0 + col;
                        *(uint32_t*)(g_hh + ix) = cvt2h(h0, h1);
                    }
                }
            }
    }
}

// ---------------- down HMMA kernel (2-expert batch, vector red scatter) ------
// CTA tile: 128 slots x 128 d-cols. warps 2(m) x 4(n), warp 64x32.
// stage (bytes): A 0 | BH 10240   (20480 total)
#define DN_ST 20480
#define DN_DYN (3*DN_ST)

__global__ __launch_bounds__(256, 2)
void down_mma(float* __restrict__ out, int ebase) {
    int e = ebase + blockIdx.z;
    int n = g_cnt[e];
    int r0 = blockIdx.y * 128;
    if (r0 >= n) return;
    int d0 = blockIdx.x * 128;

    __shared__ int toks[128];
    int tid = threadIdx.x, lane = tid & 31, wid = tid >> 5;
    uint32_t smb = s2u(dynsm);
    int hbase = g_off[e];

    if (tid < 128) {
        int r = r0 + tid;
        toks[tid] = (r < n) ? g_list[e * MAXT + r] : -1;
    }
    __syncthreads();

    int arow = tid & 127, aseg = tid >> 7;
    int brow = tid & 127, bhalf = tid >> 7;
    size_t bsrcoff = WD_H + (size_t)e * EW
                   + (size_t)(d0 + brow) * FDIM + bhalf * 16;
    uint32_t bdst = (uint32_t)(10240 + brow * (PITCH * 2) + bhalf * 32);

    auto issue = [&](int k0, int st) {
        {
            int r = r0 + arow;
            bool v = r < n;
            uint32_t d = smb + st * DN_ST + (arow * PITCH + aseg * 16) * 2;
            const __half* sh = g_hh + ((size_t)(hbase + (v ? r : 0)) * FDIM + k0 + aseg * 16);
            int sz = v ? 16 : 0;
            cp16(d,      sh,     sz);
            cp16(d + 16, sh + 8, sz);
        }
        {
            const __half* s = g_whalf + bsrcoff + k0;
            uint32_t d = smb + st * DN_ST + bdst;
            cp16(d,      s,     16);
            cp16(d + 16, s + 8, 16);
        }
    };

    float acc[4][4][4];
#pragma unroll
    for (int mt = 0; mt < 4; mt++)
#pragma unroll
        for (int nt = 0; nt < 4; nt++)
#pragma unroll
            for (int j = 0; j < 4; j++) acc[mt][nt][j] = 0.f;

    int m0 = (wid & 1) * 64, n0 = (wid >> 1) * 32;
    int mat = lane >> 3, rowin = lane & 7;

    auto compute_slab = [&](int st, int s) {
        uint32_t base = smb + st * DN_ST;
        int kc = s * 16;
        uint32_t ah[4][4];
#pragma unroll
        for (int mt = 0; mt < 4; mt++) {
            uint32_t a = base +
                ((m0 + mt * 16 + (mat & 1) * 8 + rowin) * PITCH + kc + (mat >> 1) * 8) * 2;
            ldsm4(ah[mt], a);
        }
        uint32_t bh[8];
#pragma unroll
        for (int h16 = 0; h16 < 2; h16++) {
            uint32_t a = base + 10240 +
                ((n0 + h16 * 16 + (mat >> 1) * 8 + rowin) * PITCH + kc + (mat & 1) * 8) * 2;
            ldsm4(&bh[h16 * 4], a);
        }
#pragma unroll
        for (int mt = 0; mt < 4; mt++)
#pragma unroll
            for (int nt = 0; nt < 4; nt++)
                mma16816(acc[mt][nt], ah[mt], &bh[nt * 2]);
    };

    issue(0, 0); cp_commit();
    issue(32, 1); cp_commit();

    const int C = FDIM / 32;  // 32
    int cbuf = 0, ibuf = 2;
    for (int c = 0; c < C; c++) {
        if (c + 2 < C) cp_wait1(); else cp_wait0();
        __syncthreads();
        compute_slab(cbuf, 0);
        compute_slab(cbuf, 1);
        if (c + 2 < C) {
            issue((c + 2) * 32, ibuf);
            cp_commit();
            ibuf = (ibuf == 2) ? 0 : ibuf + 1;
        }
        cbuf = (cbuf == 2) ? 0 : cbuf + 1;
    }

#pragma unroll
    for (int mt = 0; mt < 4; mt++)
#pragma unroll
        for (int nt = 0; nt < 4; nt++) {
            int rb = m0 + mt * 16 + (lane >> 2);
            int col = d0 + n0 + nt * 8 + 2 * (lane & 3);
#pragma unroll
            for (int h = 0; h < 2; h++) {
                int r = rb + h * 8;
                if (r0 + r < n) {
                    int tk = toks[r];
                    red2(out + (size_t)tk * DDIM + col,
                         acc[mt][nt][2*h], acc[mt][nt][2*h+1]);
                }
            }
        }
}

// ---------------- launch ----------------------------------------------------
extern "C" void kernel_launch(void* const* d_in, const int* in_sizes, int n_in,
                              void* d_out, int out_size) {
    const float* x  = (const float*)d_in[0];
    const float* gw = (const float*)d_in[1];
    const float* wg = (const float*)d_in[2];
    const float* wu = (const float*)d_in[3];
    const float* wd = (const float*)d_in[4];
    float* out = (float*)d_out;

    int T = in_sizes[0] / DDIM;
    int write_logits = (out_size >= T * DDIM + T * NEXP) ? 1 : 0;
    float* logits = out + (size_t)T * DDIM;

    static cudaStream_t s1 = nullptr, s2 = nullptr;
    static cudaEvent_t ev0, evR, evWD, evWuA, evWuB;
    static cudaEvent_t evG[4], evE[4];
    if (!s1) {
        cudaFuncSetAttribute(gateup_mma, cudaFuncAttributeMaxDynamicSharedMemorySize, GU_DYN);
        cudaFuncSetAttribute(down_mma,   cudaFuncAttributeMaxDynamicSharedMemorySize, DN_DYN);
        cudaStreamCreateWithFlags(&s1, cudaStreamNonBlocking);
        cudaStreamCreateWithFlags(&s2, cudaStreamNonBlocking);
        cudaEventCreateWithFlags(&ev0,   cudaEventDisableTiming);
        cudaEventCreateWithFlags(&evR,   cudaEventDisableTiming);
        cudaEventCreateWithFlags(&evWD,  cudaEventDisableTiming);
        cudaEventCreateWithFlags(&evWuA, cudaEventDisableTiming);
        cudaEventCreateWithFlags(&evWuB, cudaEventDisableTiming);
        for (int q = 0; q < 4; q++) {
            cudaEventCreateWithFlags(&evG[q], cudaEventDisableTiming);
            cudaEventCreateWithFlags(&evE[q], cudaEventDisableTiming);
        }
    }

    __half* wh;
    cudaGetSymbolAddress((void**)&wh, g_whalf);

    size_t halfW = WELEM / 2;
    int hn16 = (int)(halfW / 16);
    int hblocks = (hn16 + 255) / 256;
    int wn16 = (int)(WELEM / 16);
    int wblocks = (wn16 + 255) / 256;

    // fork root
    cudaEventRecord(ev0, 0);
    cudaStreamWaitEvent(s1, ev0, 0);
    cudaStreamWaitEvent(s2, ev0, 0);

    // cross-assigned half-tensor conversions:
    // s1: wg[0:4], then wu[4:8];  s2: wu[0:4], then wg[4:8]
    presplit_w<<<hblocks, 256, 0, s1>>>(wg, wh + WG_H, hn16);
    presplit_w<<<hblocks, 256, 0, s1>>>(wu + halfW, wh + WU_H + halfW, hn16);
    cudaEventRecord(evWuB, s1);
    presplit_w<<<hblocks, 256, 0, s2>>>(wu, wh + WU_H, hn16);
    cudaEventRecord(evWuA, s2);
    presplit_w<<<hblocks, 256, 0, s2>>>(wg + halfW, wh + WG_H + halfW, hn16);

    // default: router chain, then wd conversion
    presplit_x<<<(T * DDIM / 4 + 255) / 256, 256>>>(x, T * DDIM / 4);
    zero_out<<<(T * DDIM / 4 + 255) / 256, 256>>>(out, T * DDIM / 4);
    router_kernel<<<T, 256>>>(x, gw, logits, write_logits);
    prefix_kernel<<<1, 1>>>();
    cudaEventRecord(evR, 0);
    presplit_w<<<wblocks, 256>>>(wd, wh + WD_H, wn16);
    cudaEventRecord(evWD, 0);

    int ytiles = (T + 127) / 128;
    dim3 gg(FDIM / 64, ytiles, 2);     // 2 experts per launch
    dim3 gd(DDIM / 128, ytiles, 2);

    // s1: gateup quarters 0 (e0,e1) and 1 (e2,e3)
    cudaStreamWaitEvent(s1, evR, 0);
    cudaStreamWaitEvent(s1, evWuA, 0);
    gateup_mma<<<gg, 256, GU_DYN, s1>>>(0);
    cudaEventRecord(evG[0], s1);
    gateup_mma<<<gg, 256, GU_DYN, s1>>>(2);
    cudaEventRecord(evG[1], s1);

    // s2: gateup quarters 2 (e4,e5) and 3 (e6,e7)
    cudaStreamWaitEvent(s2, evR, 0);
    cudaStreamWaitEvent(s2, evWuB, 0);
    gateup_mma<<<gg, 256, GU_DYN, s2>>>(4);
    cudaEventRecord(evG[2], s2);
    gateup_mma<<<gg, 256, GU_DYN, s2>>>(6);
    cudaEventRecord(evG[3], s2);

    // default stream: downs per quarter, each gated on its gateup quarter
    for (int q = 0; q < 4; q++) {
        cudaStreamWaitEvent(0, evG[q], 0);   // also after evWD (in-stream order)
        down_mma<<<gd, 256, DN_DYN>>>(out, q * 2);
    }
}

// round 16
// speedup vs baseline: 1.2908x; 1.2908x over previous
#include <cuda_runtime.h>
#include <cuda_fp16.h>
#include <math.h>
#include <stdint.h>

#define NEXP 8
#define DDIM 2048
#define FDIM 1024
#define MAXT 2048
#define MAXSLOT (2*MAXT)
#define PITCH 40   // halves per 32-k row (64B data + 16B pad)

#define WELEM ((size_t)NEXP*FDIM*DDIM)   // 16777216 per tensor
#define EW    ((size_t)FDIM*DDIM)        // per-expert elements
#define WG_H ((size_t)0)
#define WU_H (WELEM)
#define WD_H (2*WELEM)

// ---------------- device scratch --------------------------------------------
__device__ int   g_cnt[NEXP];
__device__ int   g_off[NEXP];
__device__ int   g_list[NEXP*MAXT];
__device__ float g_wte[NEXP*MAXT];
__device__ __half g_xh[(size_t)MAXT*DDIM];
__device__ __half g_hh[(size_t)MAXSLOT*FDIM];
__device__ __half g_whalf[3*WELEM];   // 100 MB pre-converted fp16 weights

// ---------------- helpers ----------------------------------------------------
__device__ __forceinline__ uint32_t s2u(const void* p) {
    return (uint32_t)__cvta_generic_to_shared(p);
}
__device__ __forceinline__ void ldsm4(uint32_t* r, uint32_t a) {
    asm volatile("ldmatrix.sync.aligned.m8n8.x4.shared.b16 {%0,%1,%2,%3}, [%4];"
                 : "=r"(r[0]), "=r"(r[1]), "=r"(r[2]), "=r"(r[3]) : "r"(a));
}
__device__ __forceinline__ void mma16816(float* c, const uint32_t* a,
                                         const uint32_t* b) {
    asm volatile(
        "mma.sync.aligned.m16n8k16.row.col.f32.f16.f16.f32 "
        "{%0,%1,%2,%3}, {%4,%5,%6,%7}, {%8,%9}, {%0,%1,%2,%3};"
        : "+f"(c[0]), "+f"(c[1]), "+f"(c[2]), "+f"(c[3])
        : "r"(a[0]), "r"(a[1]), "r"(a[2]), "r"(a[3]), "r"(b[0]), "r"(b[1]));
}
__device__ __forceinline__ void cp16(uint32_t dst, const void* src, int sz) {
    asm volatile("cp.async.ca.shared.global [%0], [%1], 16, %2;"
                 :: "r"(dst), "l"(src), "r"(sz) : "memory");
}
__device__ __forceinline__ void cp_commit() {
    asm volatile("cp.async.commit_group;" ::: "memory");
}
__device__ __forceinline__ void cp_wait1() {
    asm volatile("cp.async.wait_group 1;" ::: "memory");
}
__device__ __forceinline__ void cp_wait0() {
    asm volatile("cp.async.wait_group 0;" ::: "memory");
}
__device__ __forceinline__ uint32_t pack2h(__half a, __half b) {
    return ((uint32_t)__half_as_ushort(b) << 16) | __half_as_ushort(a);
}
__device__ __forceinline__ uint32_t cvt2h(float a, float b) {
    return pack2h(__float2half_rn(a), __float2half_rn(b));
}
__device__ __forceinline__ void red2(float* addr, float a, float b) {
    asm volatile("red.global.add.v2.f32 [%0], {%1, %2};"
                 :: "l"(addr), "f"(a), "f"(b) : "memory");
}

// ---------------- small kernels ---------------------------------------------
__global__ void presplit_w(const float* __restrict__ src,
                           __half* __restrict__ dh, int n16) {
    int i = blockIdx.x * blockDim.x + threadIdx.x;
    if (i >= n16) return;
    const float4* s = (const float4*)src + i * 4;
    float4 v0 = __ldcs(s), v1 = __ldcs(s + 1), v2 = __ldcs(s + 2), v3 = __ldcs(s + 3);
    uint4 o0 = make_uint4(cvt2h(v0.x, v0.y), cvt2h(v0.z, v0.w),
                          cvt2h(v1.x, v1.y), cvt2h(v1.z, v1.w));
    uint4 o1 = make_uint4(cvt2h(v2.x, v2.y), cvt2h(v2.z, v2.w),
                          cvt2h(v3.x, v3.y), cvt2h(v3.z, v3.w));
    uint4* d = (uint4*)dh + i * 2;
    __stcs(d, o0);
    __stcs(d + 1, o1);
}

__global__ void presplit_x(const float* __restrict__ x, int n4) {
    int i = blockIdx.x * blockDim.x + threadIdx.x;
    if (blockIdx.x == 0 && threadIdx.x < NEXP) g_cnt[threadIdx.x] = 0;
    if (i >= n4) return;
    float4 v = ((const float4*)x)[i];
    ((uint2*)g_xh)[i] = make_uint2(cvt2h(v.x, v.y), cvt2h(v.z, v.w));
}

__global__ void zero_out(float* __restrict__ out, int n4) {
    int i = blockIdx.x * blockDim.x + threadIdx.x;
    if (i < n4)
        __stcs((float4*)out + i, make_float4(0.f, 0.f, 0.f, 0.f));
}

__global__ void router_kernel(const float* __restrict__ x,
                              const float* __restrict__ gw,
                              float* __restrict__ logits_out,
                              int write_logits) {
    __shared__ float xs[DDIM];
    __shared__ float lg[NEXP];
    int t = blockIdx.x;
    const float* xr = x + (size_t)t * DDIM;
    for (int i = threadIdx.x; i < DDIM; i += blockDim.x) xs[i] = xr[i];
    __syncthreads();

    int w = threadIdx.x >> 5, lane = threadIdx.x & 31;
    if (w < NEXP) {
        const float* g = gw + (size_t)w * DDIM;
        float s = 0.f;
        for (int d = lane; d < DDIM; d += 32) s = fmaf(xs[d], g[d], s);
        for (int o = 16; o; o >>= 1) s += __shfl_xor_sync(0xffffffffu, s, o);
        if (lane == 0) lg[w] = s;
    }
    __syncthreads();

    if (threadIdx.x == 0) {
        float l[NEXP], p[NEXP];
        float m = -1e30f;
        for (int e = 0; e < NEXP; e++) {
            l[e] = lg[e];
            if (write_logits) logits_out[(size_t)t * NEXP + e] = l[e];
            m = fmaxf(m, l[e]);
        }
        float se = 0.f;
        for (int e = 0; e < NEXP; e++) { p[e] = expf(l[e] - m); se += p[e]; }
        float inv = 1.f / se;
        for (int e = 0; e < NEXP; e++) p[e] *= inv;
        int i1 = 0;
        for (int e = 1; e < NEXP; e++) if (p[e] > p[i1]) i1 = e;
        int i2 = -1;
        for (int e = 0; e < NEXP; e++) {
            if (e == i1) continue;
            if (i2 < 0 || p[e] > p[i2]) i2 = e;
        }
        float s12 = p[i1] + p[i2];
        float w1 = p[i1] / s12, w2 = p[i2] / s12;
        int p1 = atomicAdd(&g_cnt[i1], 1);
        g_list[i1 * MAXT + p1] = t;
        g_wte[i1 * MAXT + p1] = w1;
        int p2 = atomicAdd(&g_cnt[i2], 1);
        g_list[i2 * MAXT + p2] = t;
        g_wte[i2 * MAXT + p2] = w2;
    }
}

__global__ void prefix_kernel() {
    int o = 0;
    for (int e = 0; e < NEXP; e++) { g_off[e] = o; o += g_cnt[e]; }
}

extern __shared__ __align__(16) char dynsm[];

// ---------------- gate+up HMMA kernel (4-expert batch) -----------------------
// CTA: 128 slots x 64 f-cols. Warps 0-3: gate (m64xn32), warps 4-7: up.
// stage (bytes): A 0 | GH 10240 | UH 15360   (20480 total)
#define GU_ST 20480
#define GU_DYN (3*GU_ST)

__global__ __launch_bounds__(256, 2)
void gateup_mma(int ebase) {
    int e = ebase + blockIdx.z;
    int n = g_cnt[e];
    int r0 = blockIdx.y * 128;
    if (r0 >= n) return;
    int f0 = blockIdx.x * 64;

    __shared__ int toks[128];
    int tid = threadIdx.x, lane = tid & 31, wid = tid >> 5;
    uint32_t smb = s2u(dynsm);

    if (tid < 128) {
        int r = r0 + tid;
        toks[tid] = (r < n) ? g_list[e * MAXT + r] : -1;
    }
    __syncthreads();

    int arow = tid & 127, aseg = tid >> 7;       // A loader
    int bq = tid >> 7, bhalf = (tid >> 6) & 1, brow = tid & 63;  // B loader
    size_t bsrcoff = (bq ? WU_H : WG_H) +
                     (size_t)e * EW + (size_t)(f0 + brow) * DDIM + bhalf * 16;
    uint32_t bdst = (uint32_t)(10240 + bq * 5120 + brow * (PITCH * 2) + bhalf * 32);

    auto issue = [&](int k0, int st) {
        {
            int tk = toks[arow];
            uint32_t d = smb + st * GU_ST + (arow * PITCH + aseg * 16) * 2;
            const __half* sh = g_xh + ((size_t)(tk < 0 ? 0 : tk) * DDIM + k0 + aseg * 16);
            int sz = (tk < 0) ? 0 : 16;
            cp16(d,      sh,     sz);
            cp16(d + 16, sh + 8, sz);
        }
        {
            const __half* s = g_whalf + bsrcoff + k0;
            uint32_t d = smb + st * GU_ST + bdst;
            cp16(d,      s,     16);
            cp16(d + 16, s + 8, 16);
        }
    };

    float acc[4][4][4];
#pragma unroll
    for (int mt = 0; mt < 4; mt++)
#pragma unroll
        for (int nt = 0; nt < 4; nt++)
#pragma unroll
            for (int j = 0; j < 4; j++) acc[mt][nt][j] = 0.f;

    int isUp = wid >> 2;
    int wid2 = wid & 3;
    int m0 = (wid2 & 1) * 64, n0 = (wid2 >> 1) * 32;
    int wsec = isUp ? 15360 : 10240;
    int mat = lane >> 3, rowin = lane & 7;

    auto compute_slab = [&](int st, int s) {
        uint32_t base = smb + st * GU_ST;
        int kc = s * 16;
        uint32_t ah[4][4];
#pragma unroll
        for (int mt = 0; mt < 4; mt++) {
            uint32_t a = base +
                ((m0 + mt * 16 + (mat & 1) * 8 + rowin) * PITCH + kc + (mat >> 1) * 8) * 2;
            ldsm4(ah[mt], a);
        }
        uint32_t bh[8];
#pragma unroll
        for (int h16 = 0; h16 < 2; h16++) {
            uint32_t a = base + wsec +
                ((n0 + h16 * 16 + (mat >> 1) * 8 + rowin) * PITCH + kc + (mat & 1) * 8) * 2;
            ldsm4(&bh[h16 * 4], a);
        }
#pragma unroll
        for (int mt = 0; mt < 4; mt++)
#pragma unroll
            for (int nt = 0; nt < 4; nt++)
                mma16816(acc[mt][nt], ah[mt], &bh[nt * 2]);
    };

    issue(0, 0); cp_commit();
    issue(32, 1); cp_commit();

    const int C = DDIM / 32;  // 64
    int cbuf = 0, ibuf = 2;
    for (int c = 0; c < C; c++) {
        if (c + 2 < C) cp_wait1(); else cp_wait0();
        __syncthreads();
        compute_slab(cbuf, 0);
        compute_slab(cbuf, 1);
        if (c + 2 < C) {
            issue((c + 2) * 32, ibuf);
            cp_commit();
            ibuf = (ibuf == 2) ? 0 : ibuf + 1;
        }
        cbuf = (cbuf == 2) ? 0 : cbuf + 1;
    }

    // ---- epilogue: gate warps publish G to smem, up warps combine + weight --
    __syncthreads();
    float* gsm = (float*)dynsm;   // 128 x 68 fp32 = 34816 B
    if (!isUp) {
#pragma unroll
        for (int mt = 0; mt < 4; mt++)
#pragma unroll
            for (int nt = 0; nt < 4; nt++) {
                int rb = m0 + mt * 16 + (lane >> 2);
                int col = n0 + nt * 8 + 2 * (lane & 3);
#pragma unroll
                for (int h = 0; h < 2; h++) {
                    int r = rb + h * 8;
                    *(float2*)(gsm + r * 68 + col) =
                        make_float2(acc[mt][nt][2*h], acc[mt][nt][2*h+1]);
                }
            }
    }
    __syncthreads();
    if (isUp) {
        int hbase = g_off[e];
#pragma unroll
        for (int mt = 0; mt < 4; mt++)
#pragma unroll
            for (int nt = 0; nt < 4; nt++) {
                int rb = m0 + mt * 16 + (lane >> 2);
                int col = n0 + nt * 8 + 2 * (lane & 3);
#pragma unroll
                for (int h = 0; h < 2; h++) {
                    int r = rb + h * 8;
                    if (r0 + r < n) {
                        float rw = g_wte[e * MAXT + r0 + r];
                        float2 g = *(float2*)(gsm + r * 68 + col);
                        float u0 = acc[mt][nt][2*h], u1 = acc[mt][nt][2*h+1];
                        float h0 = rw * g.x * u0 / (1.f + __expf(-g.x));
                        float h1 = rw * g.y * u1 / (1.f + __expf(-g.y));
                        size_t ix = (size_t)(hbase + r0 + r) * FDIM + f0 + col;
                        *(uint32_t*)(g_hh + ix) = cvt2h(h0, h1);
                    }
                }
            }
    }
}

// ---------------- down HMMA kernel (4-expert batch, vector red scatter) ------
// CTA tile: 128 slots x 128 d-cols. warps 2(m) x 4(n), warp 64x32.
// stage (bytes): A 0 | BH 10240   (20480 total)
#define DN_ST 20480
#define DN_DYN (3*DN_ST)

__global__ __launch_bounds__(256, 2)
void down_mma(float* __restrict__ out, int ebase) {
    int e = ebase + blockIdx.z;
    int n = g_cnt[e];
    int r0 = blockIdx.y * 128;
    if (r0 >= n) return;
    int d0 = blockIdx.x * 128;

    __shared__ int toks[128];
    int tid = threadIdx.x, lane = tid & 31, wid = tid >> 5;
    uint32_t smb = s2u(dynsm);
    int hbase = g_off[e];

    if (tid < 128) {
        int r = r0 + tid;
        toks[tid] = (r < n) ? g_list[e * MAXT + r] : -1;
    }
    __syncthreads();

    int arow = tid & 127, aseg = tid >> 7;
    int brow = tid & 127, bhalf = tid >> 7;
    size_t bsrcoff = WD_H + (size_t)e * EW
                   + (size_t)(d0 + brow) * FDIM + bhalf * 16;
    uint32_t bdst = (uint32_t)(10240 + brow * (PITCH * 2) + bhalf * 32);

    auto issue = [&](int k0, int st) {
        {
            int r = r0 + arow;
            bool v = r < n;
            uint32_t d = smb + st * DN_ST + (arow * PITCH + aseg * 16) * 2;
            const __half* sh = g_hh + ((size_t)(hbase + (v ? r : 0)) * FDIM + k0 + aseg * 16);
            int sz = v ? 16 : 0;
            cp16(d,      sh,     sz);
            cp16(d + 16, sh + 8, sz);
        }
        {
            const __half* s = g_whalf + bsrcoff + k0;
            uint32_t d = smb + st * DN_ST + bdst;
            cp16(d,      s,     16);
            cp16(d + 16, s + 8, 16);
        }
    };

    float acc[4][4][4];
#pragma unroll
    for (int mt = 0; mt < 4; mt++)
#pragma unroll
        for (int nt = 0; nt < 4; nt++)
#pragma unroll
            for (int j = 0; j < 4; j++) acc[mt][nt][j] = 0.f;

    int m0 = (wid & 1) * 64, n0 = (wid >> 1) * 32;
    int mat = lane >> 3, rowin = lane & 7;

    auto compute_slab = [&](int st, int s) {
        uint32_t base = smb + st * DN_ST;
        int kc = s * 16;
        uint32_t ah[4][4];
#pragma unroll
        for (int mt = 0; mt < 4; mt++) {
            uint32_t a = base +
                ((m0 + mt * 16 + (mat & 1) * 8 + rowin) * PITCH + kc + (mat >> 1) * 8) * 2;
            ldsm4(ah[mt], a);
        }
        uint32_t bh[8];
#pragma unroll
        for (int h16 = 0; h16 < 2; h16++) {
            uint32_t a = base + 10240 +
                ((n0 + h16 * 16 + (mat >> 1) * 8 + rowin) * PITCH + kc + (mat & 1) * 8) * 2;
            ldsm4(&bh[h16 * 4], a);
        }
#pragma unroll
        for (int mt = 0; mt < 4; mt++)
#pragma unroll
            for (int nt = 0; nt < 4; nt++)
                mma16816(acc[mt][nt], ah[mt], &bh[nt * 2]);
    };

    issue(0, 0); cp_commit();
    issue(32, 1); cp_commit();

    const int C = FDIM / 32;  // 32
    int cbuf = 0, ibuf = 2;
    for (int c = 0; c < C; c++) {
        if (c + 2 < C) cp_wait1(); else cp_wait0();
        __syncthreads();
        compute_slab(cbuf, 0);
        compute_slab(cbuf, 1);
        if (c + 2 < C) {
            issue((c + 2) * 32, ibuf);
            cp_commit();
            ibuf = (ibuf == 2) ? 0 : ibuf + 1;
        }
        cbuf = (cbuf == 2) ? 0 : cbuf + 1;
    }

#pragma unroll
    for (int mt = 0; mt < 4; mt++)
#pragma unroll
        for (int nt = 0; nt < 4; nt++) {
            int rb = m0 + mt * 16 + (lane >> 2);
            int col = d0 + n0 + nt * 8 + 2 * (lane & 3);
#pragma unroll
            for (int h = 0; h < 2; h++) {
                int r = rb + h * 8;
                if (r0 + r < n) {
                    int tk = toks[r];
                    red2(out + (size_t)tk * DDIM + col,
                         acc[mt][nt][2*h], acc[mt][nt][2*h+1]);
                }
            }
        }
}

// ---------------- launch ----------------------------------------------------
extern "C" void kernel_launch(void* const* d_in, const int* in_sizes, int n_in,
                              void* d_out, int out_size) {
    const float* x  = (const float*)d_in[0];
    const float* gw = (const float*)d_in[1];
    const float* wg = (const float*)d_in[2];
    const float* wu = (const float*)d_in[3];
    const float* wd = (const float*)d_in[4];
    float* out = (float*)d_out;

    int T = in_sizes[0] / DDIM;
    int write_logits = (out_size >= T * DDIM + T * NEXP) ? 1 : 0;
    float* logits = out + (size_t)T * DDIM;

    static cudaStream_t s1 = nullptr, s2 = nullptr;
    static cudaEvent_t ev0, evR, evWD, evWuA, evWuB, evE1, evE2;
    if (!s1) {
        cudaFuncSetAttribute(gateup_mma, cudaFuncAttributeMaxDynamicSharedMemorySize, GU_DYN);
        cudaFuncSetAttribute(down_mma,   cudaFuncAttributeMaxDynamicSharedMemorySize, DN_DYN);
        cudaStreamCreateWithFlags(&s1, cudaStreamNonBlocking);
        cudaStreamCreateWithFlags(&s2, cudaStreamNonBlocking);
        cudaEventCreateWithFlags(&ev0,   cudaEventDisableTiming);
        cudaEventCreateWithFlags(&evR,   cudaEventDisableTiming);
        cudaEventCreateWithFlags(&evWD,  cudaEventDisableTiming);
        cudaEventCreateWithFlags(&evWuA, cudaEventDisableTiming);
        cudaEventCreateWithFlags(&evWuB, cudaEventDisableTiming);
        cudaEventCreateWithFlags(&evE1,  cudaEventDisableTiming);
        cudaEventCreateWithFlags(&evE2,  cudaEventDisableTiming);
    }

    __half* wh;
    cudaGetSymbolAddress((void**)&wh, g_whalf);

    size_t halfW = WELEM / 2;                 // 4 experts' worth
    int hn16 = (int)(halfW / 16);
    int hblocks = (hn16 + 255) / 256;
    int wn16 = (int)(WELEM / 16);
    int wblocks = (wn16 + 255) / 256;

    // fork root
    cudaEventRecord(ev0, 0);
    cudaStreamWaitEvent(s1, ev0, 0);
    cudaStreamWaitEvent(s2, ev0, 0);

    // cross-assigned half-tensor conversions:
    // s1: wg[0:4], then wu[4:8];  s2: wu[0:4], then wg[4:8]
    presplit_w<<<hblocks, 256, 0, s1>>>(wg, wh + WG_H, hn16);
    presplit_w<<<hblocks, 256, 0, s1>>>(wu + halfW, wh + WU_H + halfW, hn16);
    cudaEventRecord(evWuB, s1);
    presplit_w<<<hblocks, 256, 0, s2>>>(wu, wh + WU_H, hn16);
    cudaEventRecord(evWuA, s2);
    presplit_w<<<hblocks, 256, 0, s2>>>(wg + halfW, wh + WG_H + halfW, hn16);

    // default stream: wd conversion first (no deps), then router chain
    presplit_w<<<wblocks, 256>>>(wd, wh + WD_H, wn16);
    cudaEventRecord(evWD, 0);
    presplit_x<<<(T * DDIM / 4 + 255) / 256, 256>>>(x, T * DDIM / 4);
    zero_out<<<(T * DDIM / 4 + 255) / 256, 256>>>(out, T * DDIM / 4);
    router_kernel<<<T, 256>>>(x, gw, logits, write_logits);
    prefix_kernel<<<1, 1>>>();
    cudaEventRecord(evR, 0);

    int ytiles = (T + 127) / 128;
    dim3 gg(FDIM / 64, ytiles, NEXP / 2);
    dim3 gd(DDIM / 128, ytiles, NEXP / 2);

    // s1: experts 0-3 (wg[0:4] in-stream; needs wu[0:4] from s2)
    cudaStreamWaitEvent(s1, evR, 0);
    cudaStreamWaitEvent(s1, evWuA, 0);
    gateup_mma<<<gg, 256, GU_DYN, s1>>>(0);
    cudaStreamWaitEvent(s1, evWD, 0);
    down_mma<<<gd, 256, DN_DYN, s1>>>(out, 0);
    cudaEventRecord(evE1, s1);

    // s2: experts 4-7 (wg[4:8] in-stream; needs wu[4:8] from s1)
    cudaStreamWaitEvent(s2, evR, 0);
    cudaStreamWaitEvent(s2, evWuB, 0);
    gateup_mma<<<gg, 256, GU_DYN, s2>>>(NEXP / 2);
    cudaStreamWaitEvent(s2, evWD, 0);
    down_mma<<<gd, 256, DN_DYN, s2>>>(out, NEXP / 2);
    cudaEventRecord(evE2, s2);

    // join
    cudaStreamWaitEvent(0, evE1, 0);
    cudaStreamWaitEvent(0, evE2, 0);
}

// round 17
// speedup vs baseline: 1.3614x; 1.0547x over previous
#include <cuda_runtime.h>
#include <cuda_fp16.h>
#include <math.h>
#include <stdint.h>

#define NEXP 8
#define DDIM 2048
#define FDIM 1024
#define MAXT 2048
#define MAXSLOT (2*MAXT)
#define PITCH 40   // halves per 32-k row (64B data + 16B pad)

#define WELEM ((size_t)NEXP*FDIM*DDIM)   // 16777216 per tensor
#define EW    ((size_t)FDIM*DDIM)        // per-expert elements
#define WG_H ((size_t)0)
#define WU_H (WELEM)
#define WD_H (2*WELEM)

// ---------------- device scratch --------------------------------------------
__device__ int   g_cnt[NEXP];
__device__ int   g_off[NEXP];
__device__ int   g_list[NEXP*MAXT];
__device__ float g_wte[NEXP*MAXT];
__device__ __half g_xh[(size_t)MAXT*DDIM];
__device__ __half g_hh[(size_t)MAXSLOT*FDIM];
__device__ __half g_whalf[3*WELEM];   // 100 MB pre-converted fp16 weights

// ---------------- helpers ----------------------------------------------------
__device__ __forceinline__ uint32_t s2u(const void* p) {
    return (uint32_t)__cvta_generic_to_shared(p);
}
__device__ __forceinline__ void ldsm4(uint32_t* r, uint32_t a) {
    asm volatile("ldmatrix.sync.aligned.m8n8.x4.shared.b16 {%0,%1,%2,%3}, [%4];"
                 : "=r"(r[0]), "=r"(r[1]), "=r"(r[2]), "=r"(r[3]) : "r"(a));
}
__device__ __forceinline__ void mma16816(float* c, const uint32_t* a,
                                         const uint32_t* b) {
    asm volatile(
        "mma.sync.aligned.m16n8k16.row.col.f32.f16.f16.f32 "
        "{%0,%1,%2,%3}, {%4,%5,%6,%7}, {%8,%9}, {%0,%1,%2,%3};"
        : "+f"(c[0]), "+f"(c[1]), "+f"(c[2]), "+f"(c[3])
        : "r"(a[0]), "r"(a[1]), "r"(a[2]), "r"(a[3]), "r"(b[0]), "r"(b[1]));
}
__device__ __forceinline__ void cp16(uint32_t dst, const void* src, int sz) {
    asm volatile("cp.async.ca.shared.global [%0], [%1], 16, %2;"
                 :: "r"(dst), "l"(src), "r"(sz) : "memory");
}
__device__ __forceinline__ void cp_commit() {
    asm volatile("cp.async.commit_group;" ::: "memory");
}
__device__ __forceinline__ void cp_wait2() {
    asm volatile("cp.async.wait_group 2;" ::: "memory");
}
__device__ __forceinline__ void cp_wait1() {
    asm volatile("cp.async.wait_group 1;" ::: "memory");
}
__device__ __forceinline__ void cp_wait0() {
    asm volatile("cp.async.wait_group 0;" ::: "memory");
}
__device__ __forceinline__ uint32_t pack2h(__half a, __half b) {
    return ((uint32_t)__half_as_ushort(b) << 16) | __half_as_ushort(a);
}
__device__ __forceinline__ uint32_t cvt2h(float a, float b) {
    return pack2h(__float2half_rn(a), __float2half_rn(b));
}
__device__ __forceinline__ void red2(float* addr, float a, float b) {
    asm volatile("red.global.add.v2.f32 [%0], {%1, %2};"
                 :: "l"(addr), "f"(a), "f"(b) : "memory");
}

// ---------------- small kernels ---------------------------------------------
__global__ void presplit_w(const float* __restrict__ src,
                           __half* __restrict__ dh, int n16) {
    int i = blockIdx.x * blockDim.x + threadIdx.x;
    if (i >= n16) return;
    const float4* s = (const float4*)src + i * 4;
    float4 v0 = __ldcs(s), v1 = __ldcs(s + 1), v2 = __ldcs(s + 2), v3 = __ldcs(s + 3);
    uint4 o0 = make_uint4(cvt2h(v0.x, v0.y), cvt2h(v0.z, v0.w),
                          cvt2h(v1.x, v1.y), cvt2h(v1.z, v1.w));
    uint4 o1 = make_uint4(cvt2h(v2.x, v2.y), cvt2h(v2.z, v2.w),
                          cvt2h(v3.x, v3.y), cvt2h(v3.z, v3.w));
    uint4* d = (uint4*)dh + i * 2;
    __stcs(d, o0);
    __stcs(d + 1, o1);
}

// converts x to fp16 AND zeroes out[] (same element count)
__global__ void presplit_x(const float* __restrict__ x,
                           float* __restrict__ out, int n4) {
    int i = blockIdx.x * blockDim.x + threadIdx.x;
    if (blockIdx.x == 0 && threadIdx.x < NEXP) g_cnt[threadIdx.x] = 0;
    if (i >= n4) return;
    float4 v = ((const float4*)x)[i];
    ((uint2*)g_xh)[i] = make_uint2(cvt2h(v.x, v.y), cvt2h(v.z, v.w));
    __stcs((float4*)out + i, make_float4(0.f, 0.f, 0.f, 0.f));
}

__global__ void router_kernel(const float* __restrict__ x,
                              const float* __restrict__ gw,
                              float* __restrict__ logits_out,
                              int write_logits) {
    __shared__ float xs[DDIM];
    __shared__ float lg[NEXP];
    int t = blockIdx.x;
    const float* xr = x + (size_t)t * DDIM;
    for (int i = threadIdx.x; i < DDIM; i += blockDim.x) xs[i] = xr[i];
    __syncthreads();

    int w = threadIdx.x >> 5, lane = threadIdx.x & 31;
    if (w < NEXP) {
        const float* g = gw + (size_t)w * DDIM;
        float s = 0.f;
        for (int d = lane; d < DDIM; d += 32) s = fmaf(xs[d], g[d], s);
        for (int o = 16; o; o >>= 1) s += __shfl_xor_sync(0xffffffffu, s, o);
        if (lane == 0) lg[w] = s;
    }
    __syncthreads();

    if (threadIdx.x == 0) {
        float l[NEXP], p[NEXP];
        float m = -1e30f;
        for (int e = 0; e < NEXP; e++) {
            l[e] = lg[e];
            if (write_logits) logits_out[(size_t)t * NEXP + e] = l[e];
            m = fmaxf(m, l[e]);
        }
        float se = 0.f;
        for (int e = 0; e < NEXP; e++) { p[e] = expf(l[e] - m); se += p[e]; }
        float inv = 1.f / se;
        for (int e = 0; e < NEXP; e++) p[e] *= inv;
        int i1 = 0;
        for (int e = 1; e < NEXP; e++) if (p[e] > p[i1]) i1 = e;
        int i2 = -1;
        for (int e = 0; e < NEXP; e++) {
            if (e == i1) continue;
            if (i2 < 0 || p[e] > p[i2]) i2 = e;
        }
        float s12 = p[i1] + p[i2];
        float w1 = p[i1] / s12, w2 = p[i2] / s12;
        int p1 = atomicAdd(&g_cnt[i1], 1);
        g_list[i1 * MAXT + p1] = t;
        g_wte[i1 * MAXT + p1] = w1;
        int p2 = atomicAdd(&g_cnt[i2], 1);
        g_list[i2 * MAXT + p2] = t;
        g_wte[i2 * MAXT + p2] = w2;
    }
}

__global__ void prefix_kernel() {
    int o = 0;
    for (int e = 0; e < NEXP; e++) { g_off[e] = o; o += g_cnt[e]; }
}

extern __shared__ __align__(16) char dynsm[];

// ---------------- gate+up HMMA kernel (4-expert batch, 4-stage) --------------
// CTA: 128 slots x 64 f-cols. Warps 0-3: gate (m64xn32), warps 4-7: up.
// stage (bytes): A 0 | GH 10240 | UH 15360   (20480 total) x 4 stages
#define GU_ST 20480
#define GU_DYN (4*GU_ST)

__global__ __launch_bounds__(256, 2)
void gateup_mma(int ebase) {
    int e = ebase + blockIdx.z;
    int n = g_cnt[e];
    int r0 = blockIdx.y * 128;
    if (r0 >= n) return;
    int f0 = blockIdx.x * 64;

    __shared__ int toks[128];
    int tid = threadIdx.x, lane = tid & 31, wid = tid >> 5;
    uint32_t smb = s2u(dynsm);

    if (tid < 128) {
        int r = r0 + tid;
        toks[tid] = (r < n) ? g_list[e * MAXT + r] : -1;
    }
    __syncthreads();

    int arow = tid & 127, aseg = tid >> 7;       // A loader
    int bq = tid >> 7, bhalf = (tid >> 6) & 1, brow = tid & 63;  // B loader
    size_t bsrcoff = (bq ? WU_H : WG_H) +
                     (size_t)e * EW + (size_t)(f0 + brow) * DDIM + bhalf * 16;
    uint32_t bdst = (uint32_t)(10240 + bq * 5120 + brow * (PITCH * 2) + bhalf * 32);

    auto issue = [&](int k0, int st) {
        {
            int tk = toks[arow];
            uint32_t d = smb + st * GU_ST + (arow * PITCH + aseg * 16) * 2;
            const __half* sh = g_xh + ((size_t)(tk < 0 ? 0 : tk) * DDIM + k0 + aseg * 16);
            int sz = (tk < 0) ? 0 : 16;
            cp16(d,      sh,     sz);
            cp16(d + 16, sh + 8, sz);
        }
        {
            const __half* s = g_whalf + bsrcoff + k0;
            uint32_t d = smb + st * GU_ST + bdst;
            cp16(d,      s,     16);
            cp16(d + 16, s + 8, 16);
        }
    };

    float acc[4][4][4];
#pragma unroll
    for (int mt = 0; mt < 4; mt++)
#pragma unroll
        for (int nt = 0; nt < 4; nt++)
#pragma unroll
            for (int j = 0; j < 4; j++) acc[mt][nt][j] = 0.f;

    int isUp = wid >> 2;
    int wid2 = wid & 3;
    int m0 = (wid2 & 1) * 64, n0 = (wid2 >> 1) * 32;
    int wsec = isUp ? 15360 : 10240;
    int mat = lane >> 3, rowin = lane & 7;

    auto compute_slab = [&](int st, int s) {
        uint32_t base = smb + st * GU_ST;
        int kc = s * 16;
        uint32_t ah[4][4];
#pragma unroll
        for (int mt = 0; mt < 4; mt++) {
            uint32_t a = base +
                ((m0 + mt * 16 + (mat & 1) * 8 + rowin) * PITCH + kc + (mat >> 1) * 8) * 2;
            ldsm4(ah[mt], a);
        }
        uint32_t bh[8];
#pragma unroll
        for (int h16 = 0; h16 < 2; h16++) {
            uint32_t a = base + wsec +
                ((n0 + h16 * 16 + (mat >> 1) * 8 + rowin) * PITCH + kc + (mat & 1) * 8) * 2;
            ldsm4(&bh[h16 * 4], a);
        }
#pragma unroll
        for (int mt = 0; mt < 4; mt++)
#pragma unroll
            for (int nt = 0; nt < 4; nt++)
                mma16816(acc[mt][nt], ah[mt], &bh[nt * 2]);
    };

    const int C = DDIM / 32;  // 64
    issue(0, 0); cp_commit();
    issue(32, 1); cp_commit();
    issue(64, 2); cp_commit();

    for (int c = 0; c < C; c++) {
        if (c + 2 < C)      cp_wait2();
        else if (c + 1 < C) cp_wait1();
        else                cp_wait0();
        __syncthreads();
        int cbuf = c & 3;
        compute_slab(cbuf, 0);
        compute_slab(cbuf, 1);
        if (c + 3 < C) {
            issue((c + 3) * 32, (c + 3) & 3);
            cp_commit();
        }
    }

    // ---- epilogue: gate warps publish G to smem, up warps combine + weight --
    __syncthreads();
    float* gsm = (float*)dynsm;   // 128 x 68 fp32 = 34816 B
    if (!isUp) {
#pragma unroll
        for (int mt = 0; mt < 4; mt++)
#pragma unroll
            for (int nt = 0; nt < 4; nt++) {
                int rb = m0 + mt * 16 + (lane >> 2);
                int col = n0 + nt * 8 + 2 * (lane & 3);
#pragma unroll
                for (int h = 0; h < 2; h++) {
                    int r = rb + h * 8;
                    *(float2*)(gsm + r * 68 + col) =
                        make_float2(acc[mt][nt][2*h], acc[mt][nt][2*h+1]);
                }
            }
    }
    __syncthreads();
    if (isUp) {
        int hbase = g_off[e];
#pragma unroll
        for (int mt = 0; mt < 4; mt++)
#pragma unroll
            for (int nt = 0; nt < 4; nt++) {
                int rb = m0 + mt * 16 + (lane >> 2);
                int col = n0 + nt * 8 + 2 * (lane & 3);
#pragma unroll
                for (int h = 0; h < 2; h++) {
                    int r = rb + h * 8;
                    if (r0 + r < n) {
                        float rw = g_wte[e * MAXT + r0 + r];
                        float2 g = *(float2*)(gsm + r * 68 + col);
                        float u0 = acc[mt][nt][2*h], u1 = acc[mt][nt][2*h+1];
                        float h0 = rw * g.x * u0 / (1.f + __expf(-g.x));
                        float h1 = rw * g.y * u1 / (1.f + __expf(-g.y));
                        size_t ix = (size_t)(hbase + r0 + r) * FDIM + f0 + col;
                        *(uint32_t*)(g_hh + ix) = cvt2h(h0, h1);
                    }
                }
            }
    }
}

// ---------------- down HMMA kernel (4-expert batch, 4-stage, red scatter) ----
// CTA tile: 128 slots x 128 d-cols. warps 2(m) x 4(n), warp 64x32.
// stage (bytes): A 0 | BH 10240   (20480 total) x 4 stages
#define DN_ST 20480
#define DN_DYN (4*DN_ST)

__global__ __launch_bounds__(256, 2)
void down_mma(float* __restrict__ out, int ebase) {
    int e = ebase + blockIdx.z;
    int n = g_cnt[e];
    int r0 = blockIdx.y * 128;
    if (r0 >= n) return;
    int d0 = blockIdx.x * 128;

    __shared__ int toks[128];
    int tid = threadIdx.x, lane = tid & 31, wid = tid >> 5;
    uint32_t smb = s2u(dynsm);
    int hbase = g_off[e];

    if (tid < 128) {
        int r = r0 + tid;
        toks[tid] = (r < n) ? g_list[e * MAXT + r] : -1;
    }
    __syncthreads();

    int arow = tid & 127, aseg = tid >> 7;
    int brow = tid & 127, bhalf = tid >> 7;
    size_t bsrcoff = WD_H + (size_t)e * EW
                   + (size_t)(d0 + brow) * FDIM + bhalf * 16;
    uint32_t bdst = (uint32_t)(10240 + brow * (PITCH * 2) + bhalf * 32);

    auto issue = [&](int k0, int st) {
        {
            int r = r0 + arow;
            bool v = r < n;
            uint32_t d = smb + st * DN_ST + (arow * PITCH + aseg * 16) * 2;
            const __half* sh = g_hh + ((size_t)(hbase + (v ? r : 0)) * FDIM + k0 + aseg * 16);
            int sz = v ? 16 : 0;
            cp16(d,      sh,     sz);
            cp16(d + 16, sh + 8, sz);
        }
        {
            const __half* s = g_whalf + bsrcoff + k0;
            uint32_t d = smb + st * DN_ST + bdst;
            cp16(d,      s,     16);
            cp16(d + 16, s + 8, 16);
        }
    };

    float acc[4][4][4];
#pragma unroll
    for (int mt = 0; mt < 4; mt++)
#pragma unroll
        for (int nt = 0; nt < 4; nt++)
#pragma unroll
            for (int j = 0; j < 4; j++) acc[mt][nt][j] = 0.f;

    int m0 = (wid & 1) * 64, n0 = (wid >> 1) * 32;
    int mat = lane >> 3, rowin = lane & 7;

    auto compute_slab = [&](int st, int s) {
        uint32_t base = smb + st * DN_ST;
        int kc = s * 16;
        uint32_t ah[4][4];
#pragma unroll
        for (int mt = 0; mt < 4; mt++) {
            uint32_t a = base +
                ((m0 + mt * 16 + (mat & 1) * 8 + rowin) * PITCH + kc + (mat >> 1) * 8) * 2;
            ldsm4(ah[mt], a);
        }
        uint32_t bh[8];
#pragma unroll
        for (int h16 = 0; h16 < 2; h16++) {
            uint32_t a = base + 10240 +
                ((n0 + h16 * 16 + (mat >> 1) * 8 + rowin) * PITCH + kc + (mat & 1) * 8) * 2;
            ldsm4(&bh[h16 * 4], a);
        }
#pragma unroll
        for (int mt = 0; mt < 4; mt++)
#pragma unroll
            for (int nt = 0; nt < 4; nt++)
                mma16816(acc[mt][nt], ah[mt], &bh[nt * 2]);
    };

    const int C = FDIM / 32;  // 32
    issue(0, 0); cp_commit();
    issue(32, 1); cp_commit();
    issue(64, 2); cp_commit();

    for (int c = 0; c < C; c++) {
        if (c + 2 < C)      cp_wait2();
        else if (c + 1 < C) cp_wait1();
        else                cp_wait0();
        __syncthreads();
        int cbuf = c & 3;
        compute_slab(cbuf, 0);
        compute_slab(cbuf, 1);
        if (c + 3 < C) {
            issue((c + 3) * 32, (c + 3) & 3);
            cp_commit();
        }
    }

#pragma unroll
    for (int mt = 0; mt < 4; mt++)
#pragma unroll
        for (int nt = 0; nt < 4; nt++) {
            int rb = m0 + mt * 16 + (lane >> 2);
            int col = d0 + n0 + nt * 8 + 2 * (lane & 3);
#pragma unroll
            for (int h = 0; h < 2; h++) {
                int r = rb + h * 8;
                if (r0 + r < n) {
                    int tk = toks[r];
                    red2(out + (size_t)tk * DDIM + col,
                         acc[mt][nt][2*h], acc[mt][nt][2*h+1]);
                }
            }
        }
}

// ---------------- launch ----------------------------------------------------
extern "C" void kernel_launch(void* const* d_in, const int* in_sizes, int n_in,
                              void* d_out, int out_size) {
    const float* x  = (const float*)d_in[0];
    const float* gw = (const float*)d_in[1];
    const float* wg = (const float*)d_in[2];
    const float* wu = (const float*)d_in[3];
    const float* wd = (const float*)d_in[4];
    float* out = (float*)d_out;

    int T = in_sizes[0] / DDIM;
    int write_logits = (out_size >= T * DDIM + T * NEXP) ? 1 : 0;
    float* logits = out + (size_t)T * DDIM;

    static cudaStream_t s1 = nullptr, s2 = nullptr;
    static cudaEvent_t ev0, evR, evWD, evWuA, evWuB, evE1, evE2;
    if (!s1) {
        cudaFuncSetAttribute(gateup_mma, cudaFuncAttributeMaxDynamicSharedMemorySize, GU_DYN);
        cudaFuncSetAttribute(down_mma,   cudaFuncAttributeMaxDynamicSharedMemorySize, DN_DYN);
        cudaStreamCreateWithFlags(&s1, cudaStreamNonBlocking);
        cudaStreamCreateWithFlags(&s2, cudaStreamNonBlocking);
        cudaEventCreateWithFlags(&ev0,   cudaEventDisableTiming);
        cudaEventCreateWithFlags(&evR,   cudaEventDisableTiming);
        cudaEventCreateWithFlags(&evWD,  cudaEventDisableTiming);
        cudaEventCreateWithFlags(&evWuA, cudaEventDisableTiming);
        cudaEventCreateWithFlags(&evWuB, cudaEventDisableTiming);
        cudaEventCreateWithFlags(&evE1,  cudaEventDisableTiming);
        cudaEventCreateWithFlags(&evE2,  cudaEventDisableTiming);
    }

    __half* wh;
    cudaGetSymbolAddress((void**)&wh, g_whalf);

    size_t halfW = WELEM / 2;                 // 4 experts' worth
    int hn16 = (int)(halfW / 16);
    int hblocks = (hn16 + 255) / 256;
    int wn16 = (int)(WELEM / 16);
    int wblocks = (wn16 + 255) / 256;

    // fork root
    cudaEventRecord(ev0, 0);
    cudaStreamWaitEvent(s1, ev0, 0);
    cudaStreamWaitEvent(s2, ev0, 0);

    // cross-assigned half-tensor conversions:
    // s1: wg[0:4], then wu[4:8];  s2: wu[0:4], then wg[4:8]
    presplit_w<<<hblocks, 256, 0, s1>>>(wg, wh + WG_H, hn16);
    presplit_w<<<hblocks, 256, 0, s1>>>(wu + halfW, wh + WU_H + halfW, hn16);
    cudaEventRecord(evWuB, s1);
    presplit_w<<<hblocks, 256, 0, s2>>>(wu, wh + WU_H, hn16);
    cudaEventRecord(evWuA, s2);
    presplit_w<<<hblocks, 256, 0, s2>>>(wg + halfW, wh + WG_H + halfW, hn16);

    // default stream: wd conversion first (no deps), then router chain
    presplit_w<<<wblocks, 256>>>(wd, wh + WD_H, wn16);
    cudaEventRecord(evWD, 0);
    presplit_x<<<(T * DDIM / 4 + 255) / 256, 256>>>(x, out, T * DDIM / 4);
    router_kernel<<<T, 256>>>(x, gw, logits, write_logits);
    prefix_kernel<<<1, 1>>>();
    cudaEventRecord(evR, 0);

    int ytiles = (T + 127) / 128;
    dim3 gg(FDIM / 64, ytiles, NEXP / 2);
    dim3 gd(DDIM / 128, ytiles, NEXP / 2);

    // s1: experts 0-3 (wg[0:4] in-stream; needs wu[0:4] from s2)
    cudaStreamWaitEvent(s1, evR, 0);
    cudaStreamWaitEvent(s1, evWuA, 0);
    gateup_mma<<<gg, 256, GU_DYN, s1>>>(0);
    cudaStreamWaitEvent(s1, evWD, 0);
    down_mma<<<gd, 256, DN_DYN, s1>>>(out, 0);
    cudaEventRecord(evE1, s1);

    // s2: experts 4-7 (wg[4:8] in-stream; needs wu[4:8] from s1)
    cudaStreamWaitEvent(s2, evR, 0);
    cudaStreamWaitEvent(s2, evWuB, 0);
    gateup_mma<<<gg, 256, GU_DYN, s2>>>(NEXP / 2);
    cudaStreamWaitEvent(s2, evWD, 0);
    down_mma<<<gd, 256, DN_DYN, s2>>>(out, NEXP / 2);
    cudaEventRecord(evE2, s2);

    // join
    cudaStreamWaitEvent(0, evE1, 0);
    cudaStreamWaitEvent(0, evE2, 0);
}